// round 1
// baseline (speedup 1.0000x reference)
#include <cuda_runtime.h>
#include <math.h>

#define NT 256
#define BC 64

// ---------------------------------------------------------------------------
// Shared-memory working set for one CTA (64 batch rows).
// Weights resident for the whole kernel; activations reused every substep.
// ---------------------------------------------------------------------------
struct __align__(16) Smem {
    float W1[52 * 64];   // padded K: rows 50,51 are zero
    float W2[64 * 64];
    float W3[64 * 8];
    float b1[64];
    float b2[64];
    float b3[8];
    float X[64 * 52];    // MLP input, ld=52 (mult of 4 -> float4 aligned)
    float H1[64 * 64];   // hidden 1, ld=64
    float H2[64 * 68];   // hidden 2, ld=68 (kills stride-64 bank conflicts in gemm3)
    float Fo[64 * 8];    // fnn output
    float state[64 * 48];// xGz state per row
    float zi[64 * 32];   // interpolated ypseq (computed once per step)
    float xcur[64 * 8];  // current RK substep x
    float uS[64 * 2];    // current control input
};

// ---------------------------------------------------------------------------
// Grey-box CSTR+flash RHS in scaled coordinates (matches _fg exactly, fp32)
// ---------------------------------------------------------------------------
__device__ __forceinline__ void fg_eval(const float* x, const float* u, float* g) {
    const float Hr  = 0.3f * x[0] + 0.7f;
    const float CAr = 0.2f * x[1] + 0.5f;
    const float CBr = 0.2f * x[2] + 0.5f;
    const float Tr  = 5.0f * x[3] + 310.0f;
    const float Hb  = 0.3f * x[4] + 0.7f;
    const float CAb = 0.2f * x[5] + 0.5f;
    const float CBb = 0.2f * x[6] + 0.5f;
    const float Tb  = 5.0f * x[7] + 310.0f;
    const float Fu  = 0.1f  * u[0] + 1.0f;
    const float Du  = 0.05f * u[1] + 0.5f;

    const float den = 3.5f * CAb + 1.1f * CBb;
    const float CAd = 3.5f * CAb / den;
    const float CBd = 1.1f * CBb / den;
    const float Fr  = sqrtf(Hr);
    const float Fb  = sqrtf(Hb);
    const float k1c = 20000.0f * expf(-3000.0f / Tr);
    const float r1  = k1c * CAr;
    const float rHr = 1.0f / Hr;
    const float rHb = 1.0f / Hb;

    const float dHr  = Fu + Du - Fr;
    const float dCAr = (Fu * (1.0f - CAr) + Du * (CAd - CAr)) * rHr - r1;
    const float dCBr = (-Fu * CBr + Du * (CBd - CBr)) * rHr + r1;
    const float dTr  = (Fu * (320.0f - Tr) + Du * (310.0f - Tr)) * rHr
                     - (200.0f / 15.0f) * rHr + r1 * (10.0f / 15.0f);
    const float dHb  = Fr - Fb - Du;
    const float dCAb = (Fr * (CAr - CAb) + Du * (CAb - CAd)) * rHb;
    const float dCBb = (Fr * (CBr - CBb) + Du * (CBb - CBd)) * rHb;
    const float dTb  = Fr * (Tr - Tb) * rHb + (200.0f / 15.0f) * rHb;

    g[0] = dHr  * (1.0f / 0.3f);
    g[1] = dCAr * (1.0f / 0.2f);
    g[2] = dCBr * (1.0f / 0.2f);
    g[3] = dTr  * (1.0f / 5.0f);
    g[4] = dHb  * (1.0f / 0.3f);
    g[5] = dCAb * (1.0f / 0.2f);
    g[6] = dCBb * (1.0f / 0.2f);
    g[7] = dTb  * (1.0f / 5.0f);
}

// ---------------------------------------------------------------------------
// 64x64 GEMM (Y = act(X @ W + b)) with 4x4 register tiling; 256 threads.
// Thread (ry=tid>>4, cx=tid&15) owns rows 4ry..4ry+3, cols 4cx..4cx+3.
// ---------------------------------------------------------------------------
template <int K, int LDX, int LDY, bool DOTANH>
__device__ __forceinline__ void gemm64(const float* __restrict__ Xs,
                                       const float* __restrict__ Ws,
                                       const float* __restrict__ bias,
                                       float* __restrict__ Ys, int tid) {
    const int cx = tid & 15;
    const int ry = tid >> 4;
    float acc[4][4];
#pragma unroll
    for (int j = 0; j < 4; j++) {
        const float bv = bias[4 * cx + j];
        acc[0][j] = bv; acc[1][j] = bv; acc[2][j] = bv; acc[3][j] = bv;
    }
    const float* xbase = Xs + 4 * ry * LDX;
#pragma unroll 2
    for (int k0 = 0; k0 < K; k0 += 4) {
        float xa[4][4];
#pragma unroll
        for (int i = 0; i < 4; i++) {
            const float4 xv = *(const float4*)(xbase + i * LDX + k0);
            xa[i][0] = xv.x; xa[i][1] = xv.y; xa[i][2] = xv.z; xa[i][3] = xv.w;
        }
#pragma unroll
        for (int kk = 0; kk < 4; kk++) {
            const float4 wv = *(const float4*)(Ws + (k0 + kk) * 64 + 4 * cx);
#pragma unroll
            for (int i = 0; i < 4; i++) {
                acc[i][0] += xa[i][kk] * wv.x;
                acc[i][1] += xa[i][kk] * wv.y;
                acc[i][2] += xa[i][kk] * wv.z;
                acc[i][3] += xa[i][kk] * wv.w;
            }
        }
    }
#pragma unroll
    for (int i = 0; i < 4; i++) {
        float4 o;
        o.x = DOTANH ? tanhf(acc[i][0]) : acc[i][0];
        o.y = DOTANH ? tanhf(acc[i][1]) : acc[i][1];
        o.z = DOTANH ? tanhf(acc[i][2]) : acc[i][2];
        o.w = DOTANH ? tanhf(acc[i][3]) : acc[i][3];
        *(float4*)(Ys + (4 * ry + i) * LDY + 4 * cx) = o;
    }
}

// ---------------------------------------------------------------------------
// Output layer: Fo[64x8] = H2[64x64] @ W3[64x8] + b3, K split 4 ways + shfl.
// ---------------------------------------------------------------------------
__device__ __forceinline__ void gemm_out(const float* __restrict__ H2,
                                         const float* __restrict__ W3,
                                         const float* __restrict__ b3,
                                         float* __restrict__ Fo, int tid) {
    const int row = tid >> 2;
    const int ks  = tid & 3;
    float acc[8];
#pragma unroll
    for (int j = 0; j < 8; j++) acc[j] = 0.0f;
    const float* hp = H2 + row * 68 + ks * 16;
#pragma unroll
    for (int kk = 0; kk < 16; kk += 4) {
        const float4 xv = *(const float4*)(hp + kk);
        float xa[4] = {xv.x, xv.y, xv.z, xv.w};
#pragma unroll
        for (int q = 0; q < 4; q++) {
            const int k = ks * 16 + kk + q;
            const float4 w0 = *(const float4*)(W3 + k * 8);
            const float4 w1 = *(const float4*)(W3 + k * 8 + 4);
            acc[0] += xa[q] * w0.x; acc[1] += xa[q] * w0.y;
            acc[2] += xa[q] * w0.z; acc[3] += xa[q] * w0.w;
            acc[4] += xa[q] * w1.x; acc[5] += xa[q] * w1.y;
            acc[6] += xa[q] * w1.z; acc[7] += xa[q] * w1.w;
        }
    }
#pragma unroll
    for (int j = 0; j < 8; j++) {
        acc[j] += __shfl_xor_sync(0xffffffffu, acc[j], 1);
        acc[j] += __shfl_xor_sync(0xffffffffu, acc[j], 2);
    }
    if (ks == 0) {
#pragma unroll
        for (int j = 0; j < 8; j++) Fo[row * 8 + j] = acc[j] + b3[j];
    }
}

// ---------------------------------------------------------------------------
// Persistent kernel: one CTA integrates 64 trajectories through all T steps.
// ---------------------------------------------------------------------------
__global__ void __launch_bounds__(NT, 1)
cstr_flash_kernel(const float* __restrict__ useq, const float* __restrict__ xGz0,
                  const float* __restrict__ gW1, const float* __restrict__ gb1,
                  const float* __restrict__ gW2, const float* __restrict__ gb2,
                  const float* __restrict__ gW3, const float* __restrict__ gb3,
                  float* __restrict__ out, int B, int T) {
    extern __shared__ char smem_raw[];
    Smem& S = *reinterpret_cast<Smem*>(smem_raw);

    const int tid  = threadIdx.x;
    const int base = blockIdx.x * BC;

    // --- load weights (pad W1 K-rows 50,51 with zeros) ---
    for (int i = tid; i < 52 * 64; i += NT) S.W1[i] = (i < 50 * 64) ? gW1[i] : 0.0f;
    for (int i = tid; i < 64 * 64; i += NT) S.W2[i] = gW2[i];
    for (int i = tid; i < 64 * 8;  i += NT) S.W3[i] = gW3[i];
    if (tid < 64) { S.b1[tid] = gb1[tid]; S.b2[tid] = gb2[tid]; }
    if (tid < 8)  { S.b3[tid] = gb3[tid]; }

    // --- load initial state ---
    for (int i = tid; i < BC * 48; i += NT) {
        const int r = i / 48, c = i - r * 48;
        S.state[i] = xGz0[(size_t)(base + r) * 48 + c];
    }
    __syncthreads();

    // per-row registers (valid for tid < 64)
    const int r = tid;
    float xG[8], xcur[8], kacc[8], u[2];
#pragma unroll
    for (int c = 0; c < 8; c++) { xcur[c] = 0.0f; kacc[c] = 0.0f; }
    u[0] = 0.0f; u[1] = 0.0f;
    if (tid < 64) {
#pragma unroll
        for (int c = 0; c < 8; c++) xG[c] = S.state[r * 48 + c];
    } else {
#pragma unroll
        for (int c = 0; c < 8; c++) xG[c] = 0.0f;
    }

#pragma unroll 1
    for (int t = 0; t < T; t++) {
        if (tid < 64) {
            // y_t = xG (pre-update)
            float* op = out + ((size_t)(base + r) * T + t) * 8;
#pragma unroll
            for (int c = 0; c < 8; c++) op[c] = xG[c];
            // load u_t
            const float* up = useq + ((size_t)(base + r) * T + t) * 2;
            u[0] = up[0]; u[1] = up[1];
            S.uS[r * 2 + 0] = u[0];
            S.uS[r * 2 + 1] = u[1];
        }
        __syncthreads();

#pragma unroll 1
        for (int s = 0; s < 4; s++) {
            // --- build MLP input X[row][0..52) = [x, z-variant, u, pad0] ---
            for (int idx = tid; idx < BC * 52; idx += NT) {
                const int row = idx / 52;
                const int k   = idx - row * 52;
                float v = 0.0f;
                if (s == 0) {
                    if (k < 48)      v = S.state[row * 48 + k];
                    else if (k < 50) v = S.uS[row * 2 + (k - 48)];
                } else if (s < 3) {
                    if (k < 8)       v = S.xcur[row * 8 + k];
                    else if (k < 40) v = S.zi[row * 32 + (k - 8)];
                    else if (k < 48) v = S.state[row * 48 + k];
                    else if (k < 50) v = S.uS[row * 2 + (k - 48)];
                } else {
                    if (k < 8)       v = S.xcur[row * 8 + k];
                    else if (k < 32) v = S.state[row * 48 + (k + 8)];   // ypseq shifted
                    else if (k < 40) v = S.state[row * 48 + (k - 32)];  // old xG
                    else if (k < 48) v = S.state[row * 48 + k];         // upseq
                    else if (k < 50) v = S.uS[row * 2 + (k - 48)];
                }
                S.X[idx] = v;
            }
            __syncthreads();

            gemm64<52, 52, 64, true >(S.X,  S.W1, S.b1, S.H1, tid);
            __syncthreads();
            gemm64<64, 64, 68, true >(S.H1, S.W2, S.b2, S.H2, tid);
            __syncthreads();
            gemm_out(S.H2, S.W3, S.b3, S.Fo, tid);
            __syncthreads();

            // --- per-row RK4 bookkeeping + grey-box physics ---
            if (tid < 64) {
                float xin[8];
#pragma unroll
                for (int c = 0; c < 8; c++) xin[c] = (s == 0) ? xG[c] : xcur[c];
                float g[8];
                fg_eval(xin, u, g);
                float kv[8];
#pragma unroll
                for (int c = 0; c < 8; c++) kv[c] = g[c] + S.Fo[r * 8 + c];

                if (s == 0) {
#pragma unroll
                    for (int c = 0; c < 8; c++) {
                        kacc[c] = kv[c];
                        xcur[c] = xG[c] + 0.005f * kv[c];
                        S.xcur[r * 8 + c] = xcur[c];
                    }
                    // zi = midpoints of [ypseq, xG] rows
#pragma unroll
                    for (int m = 0; m < 4; m++) {
#pragma unroll
                        for (int c = 0; c < 8; c++) {
                            const float a = S.state[r * 48 + 8 + m * 8 + c];
                            const float b = (m < 3) ? S.state[r * 48 + 16 + m * 8 + c]
                                                    : xG[c];
                            S.zi[r * 32 + m * 8 + c] = 0.5f * (a + b);
                        }
                    }
                } else if (s == 1) {
#pragma unroll
                    for (int c = 0; c < 8; c++) {
                        kacc[c] += 2.0f * kv[c];
                        xcur[c] = xG[c] + 0.005f * kv[c];
                        S.xcur[r * 8 + c] = xcur[c];
                    }
                } else if (s == 2) {
#pragma unroll
                    for (int c = 0; c < 8; c++) {
                        kacc[c] += 2.0f * kv[c];
                        xcur[c] = xG[c] + 0.01f * kv[c];
                        S.xcur[r * 8 + c] = xcur[c];
                    }
                } else {
#pragma unroll
                    for (int c = 0; c < 8; c++) kacc[c] += kv[c];
                    float xnew[8];
#pragma unroll
                    for (int c = 0; c < 8; c++)
                        xnew[c] = xG[c] + (0.01f / 6.0f) * kacc[c];
                    // state update: [xnew | z[16..40) | xG_old | upseq[2..8) | u]
                    float* st = &S.state[r * 48];
#pragma unroll
                    for (int c = 0; c < 8; c++) st[c] = xnew[c];
#pragma unroll
                    for (int j = 0; j < 24; j++) st[8 + j] = st[16 + j];  // dst<src: safe
#pragma unroll
                    for (int c = 0; c < 8; c++) st[32 + c] = xG[c];
#pragma unroll
                    for (int j = 0; j < 6; j++) st[40 + j] = st[42 + j];  // dst<src: safe
                    st[46] = u[0];
                    st[47] = u[1];
#pragma unroll
                    for (int c = 0; c < 8; c++) xG[c] = xnew[c];
                }
            }
            __syncthreads();
        }
    }
}

// ---------------------------------------------------------------------------
extern "C" void kernel_launch(void* const* d_in, const int* in_sizes, int n_in,
                              void* d_out, int out_size) {
    const float* useq = (const float*)d_in[0];
    const float* xGz0 = (const float*)d_in[1];
    const float* W1   = (const float*)d_in[2];
    const float* b1   = (const float*)d_in[3];
    const float* W2   = (const float*)d_in[4];
    const float* b2   = (const float*)d_in[5];
    const float* W3   = (const float*)d_in[6];
    const float* b3   = (const float*)d_in[7];
    float* out = (float*)d_out;

    const int B = in_sizes[1] / 48;
    const int T = in_sizes[0] / (B * 2);

    const int smem = (int)sizeof(Smem);
    cudaFuncSetAttribute(cstr_flash_kernel,
                         cudaFuncAttributeMaxDynamicSharedMemorySize, smem);
    cstr_flash_kernel<<<B / BC, NT, smem>>>(useq, xGz0, W1, b1, W2, b2, W3, b3,
                                            out, B, T);
}

// round 2
// speedup vs baseline: 1.4988x; 1.4988x over previous
#include <cuda_runtime.h>
#include <math.h>

#define NT 128
#define BC 32
typedef unsigned long long ull;

// packed f32x2 ops (Blackwell FFMA2 path)
#define FMA2(d, a, b, c) \
    asm("fma.rn.f32x2 %0, %1, %2, %3;" : "=l"(d) : "l"(a), "l"(b), "l"(c))
#define ADD2(d, a, b) \
    asm("add.rn.f32x2 %0, %1, %2;" : "=l"(d) : "l"(a), "l"(b))
#define UNPACK2(lo, hi, v) \
    asm("mov.b64 {%0, %1}, %2;" : "=f"(lo), "=f"(hi) : "l"(v))

__device__ __forceinline__ float tanh_fast(float x) {
    float y;
    asm("tanh.approx.f32 %0, %1;" : "=f"(y) : "f"(x));
    return y;
}

// ---------------------------------------------------------------------------
// Shared memory: weights + duplicated-activation buffers for 32 rows.
// Activations stored as {v,v} pairs so fma.rn.f32x2 needs no packing.
// ---------------------------------------------------------------------------
struct __align__(16) Smem {
    float W1[52 * 64];    // [k][j], rows 50,51 zero-padded
    float W2[64 * 64];    // [k][j]
    float W3[64 * 8];     // [k][j]
    float b1[64];
    float b2[64];
    float b3[8];
    float X2[BC * 104];   // MLP input, duplicated (52 values -> 104 floats)
    float H1[BC * 132];   // hidden1 duplicated (64 -> 128) + pad to 132
    float H2[BC * 132];   // hidden2 duplicated (64 -> 128) + pad to 132
    float yp[BC * 32];    // ypseq per row (owner-private)
};

// ---------------------------------------------------------------------------
// Grey-box CSTR+flash RHS (scaled), matches reference _fg in fp32.
// ---------------------------------------------------------------------------
__device__ __forceinline__ void fg_eval(const float* x, const float* u, float* g) {
    const float Hr  = 0.3f * x[0] + 0.7f;
    const float CAr = 0.2f * x[1] + 0.5f;
    const float CBr = 0.2f * x[2] + 0.5f;
    const float Tr  = 5.0f * x[3] + 310.0f;
    const float Hb  = 0.3f * x[4] + 0.7f;
    const float CAb = 0.2f * x[5] + 0.5f;
    const float CBb = 0.2f * x[6] + 0.5f;
    const float Tb  = 5.0f * x[7] + 310.0f;
    const float Fu  = 0.1f  * u[0] + 1.0f;
    const float Du  = 0.05f * u[1] + 0.5f;

    const float den = 3.5f * CAb + 1.1f * CBb;
    const float CAd = 3.5f * CAb / den;
    const float CBd = 1.1f * CBb / den;
    const float Fr  = sqrtf(Hr);
    const float Fb  = sqrtf(Hb);
    const float k1c = 20000.0f * expf(-3000.0f / Tr);
    const float r1  = k1c * CAr;
    const float rHr = 1.0f / Hr;
    const float rHb = 1.0f / Hb;

    const float dHr  = Fu + Du - Fr;
    const float dCAr = (Fu * (1.0f - CAr) + Du * (CAd - CAr)) * rHr - r1;
    const float dCBr = (-Fu * CBr + Du * (CBd - CBr)) * rHr + r1;
    const float dTr  = (Fu * (320.0f - Tr) + Du * (310.0f - Tr)) * rHr
                     - (200.0f / 15.0f) * rHr + r1 * (10.0f / 15.0f);
    const float dHb  = Fr - Fb - Du;
    const float dCAb = (Fr * (CAr - CAb) + Du * (CAb - CAd)) * rHb;
    const float dCBb = (Fr * (CBr - CBb) + Du * (CBb - CBd)) * rHb;
    const float dTb  = Fr * (Tr - Tb) * rHb + (200.0f / 15.0f) * rHb;

    g[0] = dHr  * (1.0f / 0.3f);
    g[1] = dCAr * (1.0f / 0.2f);
    g[2] = dCBr * (1.0f / 0.2f);
    g[3] = dTr  * (1.0f / 5.0f);
    g[4] = dHb  * (1.0f / 0.3f);
    g[5] = dCAb * (1.0f / 0.2f);
    g[6] = dCBb * (1.0f / 0.2f);
    g[7] = dTb  * (1.0f / 5.0f);
}

// ---------------------------------------------------------------------------
// 32xN GEMM with f32x2: Y2 = dup(tanh(X @ W + b)).
// 128 threads: rg=tid>>4 (4 rows each), cx=tid&15 (4 output cols = 2 pairs).
// X2 is duplicated ({v,v} at float offset 2k); W is [k][64] (pairs contiguous).
// ---------------------------------------------------------------------------
template <int KP, int LDX, int LDY>
__device__ __forceinline__ void gemm2x(const float* __restrict__ X2,
                                       const float* __restrict__ W,
                                       const float* __restrict__ bias,
                                       float* __restrict__ Y2, int tid) {
    const int cx = tid & 15;
    const int rg = tid >> 4;
    ull acc[4][2];
    const ull bp0 = *(const ull*)(bias + 4 * cx);
    const ull bp1 = *(const ull*)(bias + 4 * cx + 2);
#pragma unroll
    for (int i = 0; i < 4; i++) { acc[i][0] = bp0; acc[i][1] = bp1; }

    const float* xbase = X2 + 4 * rg * LDX;
#pragma unroll
    for (int kp = 0; kp < KP; kp++) {
        const ulonglong2 w0 = *(const ulonglong2*)(W + (2 * kp) * 64 + 4 * cx);
        const ulonglong2 w1 = *(const ulonglong2*)(W + (2 * kp + 1) * 64 + 4 * cx);
#pragma unroll
        for (int i = 0; i < 4; i++) {
            const ulonglong2 xv = *(const ulonglong2*)(xbase + i * LDX + 4 * kp);
            FMA2(acc[i][0], xv.x, w0.x, acc[i][0]);
            FMA2(acc[i][1], xv.x, w0.y, acc[i][1]);
            FMA2(acc[i][0], xv.y, w1.x, acc[i][0]);
            FMA2(acc[i][1], xv.y, w1.y, acc[i][1]);
        }
    }
#pragma unroll
    for (int i = 0; i < 4; i++) {
        float a0, a1, a2, a3;
        UNPACK2(a0, a1, acc[i][0]);
        UNPACK2(a2, a3, acc[i][1]);
        const float t0 = tanh_fast(a0), t1 = tanh_fast(a1);
        const float t2 = tanh_fast(a2), t3 = tanh_fast(a3);
        float* yp = Y2 + (4 * rg + i) * LDY + 8 * cx;
        *(float4*)(yp)     = make_float4(t0, t0, t1, t1);
        *(float4*)(yp + 4) = make_float4(t2, t2, t3, t3);
    }
}

// ---------------------------------------------------------------------------
// Persistent kernel: one CTA integrates 32 trajectories through T steps.
// Row owner = thread 4r (ks==0 of gemm_out group); holds xG/kacc/u in regs.
// ---------------------------------------------------------------------------
__global__ void __launch_bounds__(NT, 2)
cstr_flash_kernel(const float* __restrict__ useq, const float* __restrict__ xGz0,
                  const float* __restrict__ gW1, const float* __restrict__ gb1,
                  const float* __restrict__ gW2, const float* __restrict__ gb2,
                  const float* __restrict__ gW3, const float* __restrict__ gb3,
                  float* __restrict__ out, int B, int T) {
    extern __shared__ char smem_raw[];
    Smem& S = *reinterpret_cast<Smem*>(smem_raw);

    const int tid  = threadIdx.x;
    const int base = blockIdx.x * BC;

    // --- weights ---
    for (int i = tid; i < 52 * 64; i += NT) S.W1[i] = (i < 50 * 64) ? gW1[i] : 0.0f;
    for (int i = tid; i < 64 * 64; i += NT) S.W2[i] = gW2[i];
    for (int i = tid; i < 64 * 8;  i += NT) S.W3[i] = gW3[i];
    if (tid < 64) { S.b1[tid] = gb1[tid]; S.b2[tid] = gb2[tid]; }
    if (tid < 8)  { S.b3[tid] = gb3[tid]; }

    // --- per-row owner state (tid % 4 == 0, row = tid >> 2) ---
    const int row   = tid >> 2;
    const int ks    = tid & 3;
    const bool own  = (ks == 0);
    const long gr   = base + row;

    float xG[8], xcur[8], kacc[8], u0 = 0.f, u1 = 0.f;
#pragma unroll
    for (int c = 0; c < 8; c++) { xG[c] = 0.f; xcur[c] = 0.f; kacc[c] = 0.f; }

    if (own) {
        const float* x0 = xGz0 + gr * 48;
        float* Xr = S.X2 + row * 104;
        float* yr = S.yp + row * 32;
#pragma unroll
        for (int c = 0; c < 8; c++) xG[c] = x0[c];
        for (int v = 0; v < 48; v++) {          // X2[2v] = dup(x0[v])
            const float f = x0[v];
            Xr[2 * v] = f; Xr[2 * v + 1] = f;
        }
        for (int j = 0; j < 32; j++) yr[j] = x0[8 + j];
        u0 = useq[gr * T * 2 + 0];
        u1 = useq[gr * T * 2 + 1];
        Xr[96] = u0; Xr[97] = u0; Xr[98] = u1; Xr[99] = u1;
        Xr[100] = 0.f; Xr[101] = 0.f; Xr[102] = 0.f; Xr[103] = 0.f;
        // y_0 = xG_0
        float* op = out + gr * T * 8;
        *(float4*)(op)     = make_float4(xG[0], xG[1], xG[2], xG[3]);
        *(float4*)(op + 4) = make_float4(xG[4], xG[5], xG[6], xG[7]);
    }
    __syncthreads();

#pragma unroll 1
    for (int t = 0; t < T; t++) {
#pragma unroll 1
        for (int s = 0; s < 4; s++) {
            gemm2x<26, 104, 132>(S.X2, S.W1, S.b1, S.H1, tid);
            __syncthreads();
            gemm2x<32, 132, 132>(S.H1, S.W2, S.b2, S.H2, tid);
            __syncthreads();

            // --- output layer: 4 threads per row, interleaved k ---
            ull acc[4];
            acc[0] = acc[1] = acc[2] = acc[3] = 0ull;
            const float* h2r = S.H2 + row * 132;
#pragma unroll
            for (int kk = 0; kk < 16; kk++) {
                const int k = 4 * kk + ks;
                const ull xv = *(const ull*)(h2r + 2 * k);
                const ulonglong2 wa = *(const ulonglong2*)(S.W3 + k * 8);
                const ulonglong2 wb = *(const ulonglong2*)(S.W3 + k * 8 + 4);
                FMA2(acc[0], xv, wa.x, acc[0]);
                FMA2(acc[1], xv, wa.y, acc[1]);
                FMA2(acc[2], xv, wb.x, acc[2]);
                FMA2(acc[3], xv, wb.y, acc[3]);
            }
#pragma unroll
            for (int m = 1; m <= 2; m <<= 1) {
#pragma unroll
                for (int j = 0; j < 4; j++) {
                    const ull o = __shfl_xor_sync(0xffffffffu, acc[j], m);
                    ADD2(acc[j], acc[j], o);
                }
            }

            // --- owner epilogue: fnn + fg + RK4 + X rebuild ---
            if (own) {
                float fnn[8];
                UNPACK2(fnn[0], fnn[1], acc[0]);
                UNPACK2(fnn[2], fnn[3], acc[1]);
                UNPACK2(fnn[4], fnn[5], acc[2]);
                UNPACK2(fnn[6], fnn[7], acc[3]);
#pragma unroll
                for (int c = 0; c < 8; c++) fnn[c] += S.b3[c];

                float uu[2] = {u0, u1};
                float g[8];
                fg_eval((s == 0) ? xG : xcur, uu, g);
                float kv[8];
#pragma unroll
                for (int c = 0; c < 8; c++) kv[c] = g[c] + fnn[c];

                float* Xr = S.X2 + row * 104;
                float* yr = S.yp + row * 32;

                if (s == 0) {
#pragma unroll
                    for (int c = 0; c < 8; c++) {
                        kacc[c] = kv[c];
                        xcur[c] = xG[c] + 0.005f * kv[c];
                    }
                    // zi into X2[16:80]
#pragma unroll
                    for (int m = 0; m < 4; m++) {
#pragma unroll
                        for (int c = 0; c < 8; c += 2) {
                            const float a0 = yr[8 * m + c];
                            const float a1 = yr[8 * m + c + 1];
                            const float n0 = (m < 3) ? yr[8 * (m + 1) + c]     : xG[c];
                            const float n1 = (m < 3) ? yr[8 * (m + 1) + c + 1] : xG[c + 1];
                            const float z0 = 0.5f * (a0 + n0);
                            const float z1 = 0.5f * (a1 + n1);
                            *(float4*)(Xr + 16 + 2 * (8 * m + c)) =
                                make_float4(z0, z0, z1, z1);
                        }
                    }
                } else if (s == 1) {
#pragma unroll
                    for (int c = 0; c < 8; c++) {
                        kacc[c] += 2.0f * kv[c];
                        xcur[c] = xG[c] + 0.005f * kv[c];
                    }
                } else if (s == 2) {
#pragma unroll
                    for (int c = 0; c < 8; c++) {
                        kacc[c] += 2.0f * kv[c];
                        xcur[c] = xG[c] + 0.01f * kv[c];
                    }
                    // zs = [yp[8:32], xG] into X2[16:80]
#pragma unroll
                    for (int q = 0; q < 32; q += 2) {
                        const float z0 = (q < 24)     ? yr[8 + q]     : xG[q - 24];
                        const float z1 = (q + 1 < 24) ? yr[8 + q + 1] : xG[q + 1 - 24];
                        *(float4*)(Xr + 16 + 2 * q) = make_float4(z0, z0, z1, z1);
                    }
                } else {
#pragma unroll
                    for (int c = 0; c < 8; c++) kacc[c] += kv[c];
                    float xnew[8];
#pragma unroll
                    for (int c = 0; c < 8; c++)
                        xnew[c] = xG[c] + (0.01f / 6.0f) * kacc[c];
                    // yp <- [yp[8:32], xG]   (ascending copy: dst < src, safe)
#pragma unroll
                    for (int j = 0; j < 24; j++) yr[j] = yr[j + 8];
#pragma unroll
                    for (int c = 0; c < 8; c++) yr[24 + c] = xG[c];
                    // upseq shift left by 2 (dup floats X2[80:96]), append u
#pragma unroll
                    for (int q = 0; q < 6; q++) {
                        Xr[80 + 2 * q]     = Xr[84 + 2 * q];
                        Xr[80 + 2 * q + 1] = Xr[84 + 2 * q + 1];
                    }
                    Xr[92] = u0; Xr[93] = u0; Xr[94] = u1; Xr[95] = u1;
#pragma unroll
                    for (int c = 0; c < 8; c++) xG[c] = xnew[c];
                    if (t + 1 < T) {
                        // next u
                        u0 = useq[(gr * T + t + 1) * 2 + 0];
                        u1 = useq[(gr * T + t + 1) * 2 + 1];
                        Xr[96] = u0; Xr[97] = u0; Xr[98] = u1; Xr[99] = u1;
                        // y_{t+1} = xG_{t+1}
                        float* op = out + (gr * T + t + 1) * 8;
                        *(float4*)(op)     = make_float4(xG[0], xG[1], xG[2], xG[3]);
                        *(float4*)(op + 4) = make_float4(xG[4], xG[5], xG[6], xG[7]);
                    }
                }
                // xcur into X2[0:16] (dup) — for s==3 this writes xnew
                const float* xw = (s == 3) ? xG : xcur;
#pragma unroll
                for (int c = 0; c < 8; c += 2) {
                    *(float4*)(Xr + 2 * c) = make_float4(xw[c], xw[c],
                                                         xw[c + 1], xw[c + 1]);
                }
            }
            __syncthreads();
        }
    }
}

// ---------------------------------------------------------------------------
extern "C" void kernel_launch(void* const* d_in, const int* in_sizes, int n_in,
                              void* d_out, int out_size) {
    const float* useq = (const float*)d_in[0];
    const float* xGz0 = (const float*)d_in[1];
    const float* W1   = (const float*)d_in[2];
    const float* b1   = (const float*)d_in[3];
    const float* W2   = (const float*)d_in[4];
    const float* b2   = (const float*)d_in[5];
    const float* W3   = (const float*)d_in[6];
    const float* b3   = (const float*)d_in[7];
    float* out = (float*)d_out;

    const int B = in_sizes[1] / 48;
    const int T = in_sizes[0] / (B * 2);

    const int smem = (int)sizeof(Smem);
    cudaFuncSetAttribute(cstr_flash_kernel,
                         cudaFuncAttributeMaxDynamicSharedMemorySize, smem);
    cstr_flash_kernel<<<B / BC, NT, smem>>>(useq, xGz0, W1, b1, W2, b2, W3, b3,
                                            out, B, T);
}